// round 14
// baseline (speedup 1.0000x reference)
#include <cuda_runtime.h>
#include <math.h>
#include <stdint.h>

#define Gn 8
#define Hn 64
#define In 64
#define Bn 32
#define Tn 1000
#define XSTR (Gn * In)   // 512 floats per (b,t)
#define RS 16            // xq ring slots (steps)

// ---------------- packed f32x2 helpers (sm_103a) ----------------
__device__ __forceinline__ uint64_t ffma2(uint64_t a, uint64_t b, uint64_t c) {
    uint64_t d;
    asm("fma.rn.f32x2 %0, %1, %2, %3;" : "=l"(d) : "l"(a), "l"(b), "l"(c));
    return d;
}
__device__ __forceinline__ uint64_t fadd2(uint64_t a, uint64_t b) {
    uint64_t d;
    asm("add.rn.f32x2 %0, %1, %2;" : "=l"(d) : "l"(a), "l"(b));
    return d;
}
__device__ __forceinline__ uint64_t pack2(float lo, float hi) {
    uint64_t d;
    asm("mov.b64 %0, {%1, %2};" : "=l"(d) : "f"(lo), "f"(hi));
    return d;
}
__device__ __forceinline__ float2 unpack2(uint64_t v) {
    float lo, hi;
    asm("mov.b64 {%0, %1}, %2;" : "=f"(lo), "=f"(hi) : "l"(v));
    return make_float2(lo, hi);
}
__device__ __forceinline__ float fsig(float x) {
    return __fdividef(1.f, 1.f + __expf(-x));
}

// Three 32-wide partial dots (half of rows r,z,n) sharing ONE vector read.
// wr/wz/wn: 8 ulonglong2 (32 floats each). 48 ffma2, 6 chains of depth 8.
__device__ __forceinline__ float3 dot32x3(const ulonglong2* wr, const ulonglong2* wz,
                                          const ulonglong2* wn, const float* v) {
    const ulonglong2* v2 = (const ulonglong2*)v;
    uint64_t r0 = 0ull, r1 = 0ull;
    uint64_t z0 = 0ull, z1 = 0ull;
    uint64_t n0 = 0ull, n1 = 0ull;
#pragma unroll
    for (int q = 0; q < 8; q++) {
        ulonglong2 hv = v2[q];
        r0 = ffma2(wr[q].x, hv.x, r0);
        r1 = ffma2(wr[q].y, hv.y, r1);
        z0 = ffma2(wz[q].x, hv.x, z0);
        z1 = ffma2(wz[q].y, hv.y, z1);
        n0 = ffma2(wn[q].x, hv.x, n0);
        n1 = ffma2(wn[q].y, hv.y, n1);
    }
    float2 fr = unpack2(fadd2(r0, r1));
    float2 fz = unpack2(fadd2(z0, z1));
    float2 fn = unpack2(fadd2(n0, n1));
    return make_float3(fr.x + fr.y, fz.x + fz.y, fn.x + fn.y);
}

// Two 64-wide dots sharing one vector read (producer).
__device__ __forceinline__ float2 dot64x2(const ulonglong2* wA, const ulonglong2* wB,
                                          const float* v, float sA, float sB) {
    const ulonglong2* v2 = (const ulonglong2*)v;
    uint64_t a0 = pack2(sA, 0.f), a1 = 0ull, a2 = 0ull, a3 = 0ull;
    uint64_t b0 = pack2(sB, 0.f), b1 = 0ull, b2 = 0ull, b3 = 0ull;
#pragma unroll
    for (int q = 0; q < 16; q += 2) {
        ulonglong2 va = v2[q];
        ulonglong2 vb = v2[q + 1];
        a0 = ffma2(wA[q].x,     va.x, a0);
        a1 = ffma2(wA[q].y,     va.y, a1);
        a2 = ffma2(wA[q + 1].x, vb.x, a2);
        a3 = ffma2(wA[q + 1].y, vb.y, a3);
        b0 = ffma2(wB[q].x,     va.x, b0);
        b1 = ffma2(wB[q].y,     va.y, b1);
        b2 = ffma2(wB[q + 1].x, vb.x, b2);
        b3 = ffma2(wB[q + 1].y, vb.y, b3);
    }
    float2 fa = unpack2(fadd2(fadd2(a0, a1), fadd2(a2, a3)));
    float2 fb = unpack2(fadd2(fadd2(b0, b1), fadd2(b2, b3)));
    return make_float2(fa.x + fa.y, fb.x + fb.y);
}

#define SCAN_BAR() asm volatile("bar.sync 1, 128;" ::: "memory")
#define PROD_BAR() asm volatile("bar.sync 2, 96;"  ::: "memory")

// ---------------------------------------------------------------------------
// One block per (b,g); 224 threads.
//  Threads 0..127  (warps 0-3): scan. Lane pair (2e,2e+1) owns K-halves of
//     Whh rows {e,64+e,128+e}; shfl_xor(1) combines; 1 named bar/step.
//  Threads 128..223 (warps 4-6): producer. Thread p owns Wih rows {p, p+96};
//     writes xp into a 16-step smem ring; volatile counters decouple.
// grid = 256, 2 blocks/SM.
// ---------------------------------------------------------------------------
__global__ void __launch_bounds__(224, 2) gru_kernel(
    const float* __restrict__ x,
    const float* __restrict__ h0,
    const float* __restrict__ Wih,
    const float* __restrict__ Whh,
    const float* __restrict__ bih,
    const float* __restrict__ bhh,
    float* __restrict__ out)
{
    const int bg  = blockIdx.x;
    const int b   = bg >> 3;
    const int g   = bg & 7;
    const int tid = threadIdx.x;

    __shared__ __align__(16) float xq[RS][192];   // xp ring (producer -> scan)
    __shared__ __align__(16) float xs[4][64];     // staged x rows (producer)
    __shared__ __align__(16) float hbuf[2][64];   // double-buffered h
    __shared__ int prod_steps;
    __shared__ int cons_steps;

    if (tid == 0) { prod_steps = 0; cons_steps = 0; }
    __syncthreads();

    volatile int* vprod = (volatile int*)&prod_steps;
    volatile int* vcons = (volatile int*)&cons_steps;

    if (tid >= 128) {
        // ============================ PRODUCER ============================
        const int p = tid - 128;   // 0..95; owns Wih rows p and p+96
        ulonglong2 wA[16], wB[16];
        {
            const ulonglong2* q;
            q = (const ulonglong2*)&Wih[((size_t)g * 192 + p) * In];
#pragma unroll
            for (int i = 0; i < 16; i++) wA[i] = q[i];
            q = (const ulonglong2*)&Wih[((size_t)g * 192 + p + 96) * In];
#pragma unroll
            for (int i = 0; i < 16; i++) wB[i] = q[i];
        }
        const float bA = bih[g * 192 + p];
        const float bB = bih[g * 192 + p + 96];

        const float* xsrc = x + ((size_t)b * Tn) * XSTR + g * In;

        for (int pg = 0; pg < Tn / 4; pg++) {
            const int lim = 4 * pg + 4 - RS;
            if (lim > 0) { while (*vcons < lim) {} }

            if (p < 64) {
#pragma unroll
                for (int u = 0; u < 4; u++)
                    xs[u][p] = __ldcs(&xsrc[(size_t)(4 * pg + u) * XSTR + p]);
            }
            PROD_BAR();

#pragma unroll
            for (int u = 0; u < 4; u++) {
                const int t = 4 * pg + u;
                float2 d = dot64x2(wA, wB, xs[u], bA, bB);
                float* slot = xq[t & (RS - 1)];
                slot[p]      = d.x;
                slot[p + 96] = d.y;
            }
            __threadfence_block();
            PROD_BAR();
            if (p == 0) *vprod = 4 * pg + 4;
        }
        return;
    }

    // ============================== SCAN ==============================
    const int e    = tid >> 1;   // element 0..63
    const int half = tid & 1;    // K-half

    ulonglong2 wr[8], wz[8], wn[8];
    {
        const ulonglong2* q;
        q = (const ulonglong2*)&Whh[((size_t)g * 192 + e) * Hn + half * 32];
#pragma unroll
        for (int i = 0; i < 8; i++) wr[i] = q[i];
        q = (const ulonglong2*)&Whh[((size_t)g * 192 + 64 + e) * Hn + half * 32];
#pragma unroll
        for (int i = 0; i < 8; i++) wz[i] = q[i];
        q = (const ulonglong2*)&Whh[((size_t)g * 192 + 128 + e) * Hn + half * 32];
#pragma unroll
        for (int i = 0; i < 8; i++) wn[i] = q[i];
    }
    const float br = bhh[g * 192 + e];
    const float bz = bhh[g * 192 + 64 + e];
    const float bn = bhh[g * 192 + 128 + e];

    float hreg = h0[((size_t)g * Bn + b) * Hn + e];
    if (half == 0) hbuf[0][e] = hreg;
    float* outp = out + (size_t)b * Tn * (Gn * Hn) + g * Hn + e;

    SCAN_BAR();   // hbuf[0] visible to all scan warps

    for (int t = 0; t < Tn; t++) {
        if ((t & 3) == 0) {
            if (tid == 0) *vcons = t;
            const int need = (t + 4 < Tn) ? (t + 4) : Tn;
            while (*vprod < need) {}
            __threadfence_block();
        }

        // xq slot loads issued before the dot (latency hides under FFMA2)
        const float* slot = xq[t & (RS - 1)];
        const float xr = slot[e];
        const float xz = slot[64 + e];
        const float xn = slot[128 + e];

        float3 d = dot32x3(wr, wz, wn, &hbuf[t & 1][half * 32]);
        // combine the two K-halves (adjacent lanes, same warp)
        float vr = d.x + __shfl_xor_sync(0xFFFFFFFFu, d.x, 1);
        float vz = d.y + __shfl_xor_sync(0xFFFFFFFFu, d.y, 1);
        float vn = d.z + __shfl_xor_sync(0xFFFFFFFFu, d.z, 1);

        float rr = fsig(xr + (br + vr));
        float zz = fsig(xz + (bz + vz));
        float aa = xn + rr * (bn + vn);
        float nn = __fmaf_rn(2.f, fsig(2.f * aa), -1.f);
        float hn = nn + zz * (hreg - nn);
        hreg = hn;
        if (half == 0) {
            hbuf[(t + 1) & 1][e] = hn;
            __stcs(&outp[(size_t)t * (Gn * Hn)], hn);
        }

        SCAN_BAR();   // h(t) writes ordered before h(t+1) reads; xq reads done
    }

    if (half == 0) {
        out[(size_t)Bn * Tn * (Gn * Hn) + ((size_t)g * Bn + b) * Hn + e] = hreg;
    }
}

// ---------------------------------------------------------------------------
extern "C" void kernel_launch(void* const* d_in, const int* in_sizes, int n_in,
                              void* d_out, int out_size)
{
    const float* x   = (const float*)d_in[0];
    const float* h0  = (const float*)d_in[1];
    const float* Wih = (const float*)d_in[2];
    const float* Whh = (const float*)d_in[3];
    const float* bih = (const float*)d_in[4];
    const float* bhh = (const float*)d_in[5];
    float* out = (float*)d_out;

    gru_kernel<<<Bn * Gn, 224>>>(x, h0, Wih, Whh, bih, bhh, out);
}

// round 15
// speedup vs baseline: 1.8250x; 1.8250x over previous
#include <cuda_runtime.h>
#include <math.h>
#include <stdint.h>

#define Gn 8
#define Hn 64
#define In 64
#define Bn 32
#define Tn 1000
#define XSTR (Gn * In)   // 512 floats per (b,t)
#define RS 16            // xq ring slots (steps)

// ---------------- packed f32x2 helpers (sm_103a) ----------------
__device__ __forceinline__ uint64_t ffma2(uint64_t a, uint64_t b, uint64_t c) {
    uint64_t d;
    asm("fma.rn.f32x2 %0, %1, %2, %3;" : "=l"(d) : "l"(a), "l"(b), "l"(c));
    return d;
}
__device__ __forceinline__ uint64_t fadd2(uint64_t a, uint64_t b) {
    uint64_t d;
    asm("add.rn.f32x2 %0, %1, %2;" : "=l"(d) : "l"(a), "l"(b));
    return d;
}
__device__ __forceinline__ uint64_t pack2(float lo, float hi) {
    uint64_t d;
    asm("mov.b64 %0, {%1, %2};" : "=l"(d) : "f"(lo), "f"(hi));
    return d;
}
__device__ __forceinline__ float2 unpack2(uint64_t v) {
    float lo, hi;
    asm("mov.b64 {%0, %1}, %2;" : "=f"(lo), "=f"(hi) : "l"(v));
    return make_float2(lo, hi);
}
__device__ __forceinline__ float fsig(float x) {
    return __fdividef(1.f, 1.f + __expf(-x));
}

// Three 64-wide dots (rows r,z,n) sharing ONE broadcast vector read.
__device__ __forceinline__ float3 dot64x3(const ulonglong2* wr, const ulonglong2* wz,
                                          const ulonglong2* wn, const float* v,
                                          float sr, float sz, float sn) {
    const ulonglong2* v2 = (const ulonglong2*)v;
    uint64_t r0 = pack2(sr, 0.f), r1 = 0ull;
    uint64_t z0 = pack2(sz, 0.f), z1 = 0ull;
    uint64_t n0 = pack2(sn, 0.f), n1 = 0ull;
#pragma unroll
    for (int q = 0; q < 16; q++) {
        ulonglong2 hv = v2[q];
        r0 = ffma2(wr[q].x, hv.x, r0);
        r1 = ffma2(wr[q].y, hv.y, r1);
        z0 = ffma2(wz[q].x, hv.x, z0);
        z1 = ffma2(wz[q].y, hv.y, z1);
        n0 = ffma2(wn[q].x, hv.x, n0);
        n1 = ffma2(wn[q].y, hv.y, n1);
    }
    float2 fr = unpack2(fadd2(r0, r1));
    float2 fz = unpack2(fadd2(z0, z1));
    float2 fn = unpack2(fadd2(n0, n1));
    return make_float3(fr.x + fr.y, fz.x + fz.y, fn.x + fn.y);
}

__device__ __forceinline__ void named_bar(int id) {
    asm volatile("bar.sync %0, 64;" :: "r"(id) : "memory");
}

// ---------------------------------------------------------------------------
// One block = TWO independent R13 instances; grid = 128 (1 block/SM).
//  quad 0 (warps 0,1 / SMSP 0,1): scan  inst0
//  quad 1 (warps 2,3 / SMSP 2,3): scan  inst1
//  quad 2 (warps 4,5 / SMSP 0,1): prod  inst0
//  quad 3 (warps 6,7 / SMSP 2,3): prod  inst1
// -> every SMSP carries exactly 1 scan + 1 producer warp.
// ---------------------------------------------------------------------------
__global__ void __launch_bounds__(256, 1) gru_kernel(
    const float* __restrict__ x,
    const float* __restrict__ h0,
    const float* __restrict__ Wih,
    const float* __restrict__ Whh,
    const float* __restrict__ bih,
    const float* __restrict__ bhh,
    float* __restrict__ out)
{
    const int tid  = threadIdx.x;
    const int quad = tid >> 6;     // 0..3
    const int e    = tid & 63;     // element 0..63
    const int inst = quad & 1;     // instance 0/1
    const int bg   = 2 * blockIdx.x + inst;
    const int b    = bg >> 3;
    const int g    = bg & 7;

    __shared__ __align__(16) float xq[2][RS][192];  // per-inst xp ring
    __shared__ __align__(16) float xs[2][4][64];    // per-inst staged x rows
    __shared__ __align__(16) float hbuf[2][2][64];  // per-inst dbl-buffered h
    __shared__ int prodc[2];
    __shared__ int consc[2];

    if (tid < 2) { prodc[tid] = 0; consc[tid] = 0; }
    __syncthreads();

    volatile int* vprod = (volatile int*)&prodc[inst];
    volatile int* vcons = (volatile int*)&consc[inst];

    if (quad >= 2) {
        // ============================ PRODUCER ============================
        const int barid = 3 + inst;
        ulonglong2 wr[16], wz[16], wn[16];
        {
            const ulonglong2* p;
            p = (const ulonglong2*)&Wih[((size_t)g * 192 + e) * In];
#pragma unroll
            for (int q = 0; q < 16; q++) wr[q] = p[q];
            p = (const ulonglong2*)&Wih[((size_t)g * 192 + 64 + e) * In];
#pragma unroll
            for (int q = 0; q < 16; q++) wz[q] = p[q];
            p = (const ulonglong2*)&Wih[((size_t)g * 192 + 128 + e) * In];
#pragma unroll
            for (int q = 0; q < 16; q++) wn[q] = p[q];
        }
        const float br = bih[g * 192 + e];
        const float bz = bih[g * 192 + 64 + e];
        const float bn = bih[g * 192 + 128 + e];

        const float* xsrc = x + ((size_t)b * Tn) * XSTR + g * In;

        for (int p = 0; p < Tn / 4; p++) {
            const int lim = 4 * p + 4 - RS;
            if (lim > 0) { while (*vcons < lim) {} }

#pragma unroll
            for (int u = 0; u < 4; u++)
                xs[inst][u][e] = __ldcs(&xsrc[(size_t)(4 * p + u) * XSTR + e]);
            named_bar(barid);   // xs visible to both producer warps

#pragma unroll
            for (int u = 0; u < 4; u++) {
                const int t = 4 * p + u;
                float3 d = dot64x3(wr, wz, wn, xs[inst][u], br, bz, bn);
                float* slot = xq[inst][t & (RS - 1)];
                slot[e]       = d.x;
                slot[64 + e]  = d.y;
                slot[128 + e] = d.z;
            }
            __threadfence_block();
            named_bar(barid);   // writes done; xs WAR-safe for next group
            if (e == 0) *vprod = 4 * p + 4;
        }
        return;
    }

    // ============================== SCAN ==============================
    const int barid = 1 + inst;
    ulonglong2 wr[16], wz[16], wn[16];
    {
        const ulonglong2* p;
        p = (const ulonglong2*)&Whh[((size_t)g * 192 + e) * Hn];
#pragma unroll
        for (int q = 0; q < 16; q++) wr[q] = p[q];
        p = (const ulonglong2*)&Whh[((size_t)g * 192 + 64 + e) * Hn];
#pragma unroll
        for (int q = 0; q < 16; q++) wz[q] = p[q];
        p = (const ulonglong2*)&Whh[((size_t)g * 192 + 128 + e) * Hn];
#pragma unroll
        for (int q = 0; q < 16; q++) wn[q] = p[q];
    }
    const float br = bhh[g * 192 + e];
    const float bz = bhh[g * 192 + 64 + e];
    const float bn = bhh[g * 192 + 128 + e];

    float hreg = h0[((size_t)g * Bn + b) * Hn + e];
    hbuf[inst][0][e] = hreg;
    float* outp = out + (size_t)b * Tn * (Gn * Hn) + g * Hn + e;

    named_bar(barid);   // hbuf[0] visible to both scan warps

    for (int t = 0; t < Tn; t++) {
        if ((t & 3) == 0) {
            if (e == 0) *vcons = t;
            const int need = (t + 4 < Tn) ? (t + 4) : Tn;
            while (*vprod < need) {}
            __threadfence_block();
        }

        // xq loads issued BEFORE the dot: LDS latency hides under FFMA2
        const float* slot = xq[inst][t & (RS - 1)];
        const float xr = slot[e];
        const float xz = slot[64 + e];
        const float xn = slot[128 + e];

        float3 d = dot64x3(wr, wz, wn, hbuf[inst][t & 1], br, bz, bn);

        float rr = fsig(xr + d.x);
        float zz = fsig(xz + d.y);
        float aa = xn + rr * d.z;
        float nn = __fmaf_rn(2.f, fsig(2.f * aa), -1.f);
        float hn = nn + zz * (hreg - nn);
        hreg = hn;
        hbuf[inst][(t + 1) & 1][e] = hn;
        __stcs(&outp[(size_t)t * (Gn * Hn)], hn);

        named_bar(barid);   // h(t) writes ordered before h(t+1) reads
    }

    out[(size_t)Bn * Tn * (Gn * Hn) + ((size_t)g * Bn + b) * Hn + e] = hreg;
}

// ---------------------------------------------------------------------------
extern "C" void kernel_launch(void* const* d_in, const int* in_sizes, int n_in,
                              void* d_out, int out_size)
{
    const float* x   = (const float*)d_in[0];
    const float* h0  = (const float*)d_in[1];
    const float* Wih = (const float*)d_in[2];
    const float* Whh = (const float*)d_in[3];
    const float* bih = (const float*)d_in[4];
    const float* bhh = (const float*)d_in[5];
    float* out = (float*)d_out;

    gru_kernel<<<(Bn * Gn) / 2, 256>>>(x, h0, Wih, Whh, bih, bhh, out);
}

// round 16
// speedup vs baseline: 2.1118x; 1.1571x over previous
#include <cuda_runtime.h>
#include <cuda_fp16.h>
#include <math.h>
#include <stdint.h>
#include <string.h>

#define Gn 8
#define Hn 64
#define In 64
#define Bn 32
#define Tn 1000
#define XSTR (Gn * In)   // 512 floats per (b,t)
#define RS 16            // xq ring slots (steps)

// ---------------- packed f32x2 helpers (sm_103a) ----------------
__device__ __forceinline__ uint64_t ffma2(uint64_t a, uint64_t b, uint64_t c) {
    uint64_t d;
    asm("fma.rn.f32x2 %0, %1, %2, %3;" : "=l"(d) : "l"(a), "l"(b), "l"(c));
    return d;
}
__device__ __forceinline__ uint64_t fadd2(uint64_t a, uint64_t b) {
    uint64_t d;
    asm("add.rn.f32x2 %0, %1, %2;" : "=l"(d) : "l"(a), "l"(b));
    return d;
}
__device__ __forceinline__ uint64_t pack2(float lo, float hi) {
    uint64_t d;
    asm("mov.b64 %0, {%1, %2};" : "=l"(d) : "f"(lo), "f"(hi));
    return d;
}
__device__ __forceinline__ float2 unpack2(uint64_t v) {
    float lo, hi;
    asm("mov.b64 {%0, %1}, %2;" : "=f"(lo), "=f"(hi) : "l"(v));
    return make_float2(lo, hi);
}
__device__ __forceinline__ float fsig(float x) {
    return __fdividef(1.f, 1.f + __expf(-x));
}
__device__ __forceinline__ uint32_t f2_h2(float lo, float hi) {
    __half2 h = __floats2half2_rn(lo, hi);   // .x = lo, .y = hi
    uint32_t u;
    memcpy(&u, &h, 4);
    return u;
}

// Three 64-wide f32 dots (rows r,z,n) sharing ONE broadcast vector read.
__device__ __forceinline__ float3 dot64x3(const ulonglong2* wr, const ulonglong2* wz,
                                          const ulonglong2* wn, const float* v,
                                          float sr, float sz, float sn) {
    const ulonglong2* v2 = (const ulonglong2*)v;
    uint64_t r0 = pack2(sr, 0.f), r1 = 0ull;
    uint64_t z0 = pack2(sz, 0.f), z1 = 0ull;
    uint64_t n0 = pack2(sn, 0.f), n1 = 0ull;
#pragma unroll
    for (int q = 0; q < 16; q++) {
        ulonglong2 hv = v2[q];
        r0 = ffma2(wr[q].x, hv.x, r0);
        r1 = ffma2(wr[q].y, hv.y, r1);
        z0 = ffma2(wz[q].x, hv.x, z0);
        z1 = ffma2(wz[q].y, hv.y, z1);
        n0 = ffma2(wn[q].x, hv.x, n0);
        n1 = ffma2(wn[q].y, hv.y, n1);
    }
    float2 fr = unpack2(fadd2(r0, r1));
    float2 fz = unpack2(fadd2(z0, z1));
    float2 fn = unpack2(fadd2(n0, n1));
    return make_float3(fr.x + fr.y, fz.x + fz.y, fn.x + fn.y);
}

__device__ __forceinline__ void mma_16x8x16(float& d0, float& d1, float& d2, float& d3,
                                            uint32_t a0, uint32_t a1, uint32_t a2, uint32_t a3,
                                            uint32_t b0, uint32_t b1) {
    asm volatile(
        "mma.sync.aligned.m16n8k16.row.col.f32.f16.f16.f32 "
        "{%0,%1,%2,%3}, {%4,%5,%6,%7}, {%8,%9}, {%0,%1,%2,%3};"
        : "+f"(d0), "+f"(d1), "+f"(d2), "+f"(d3)
        : "r"(a0), "r"(a1), "r"(a2), "r"(a3), "r"(b0), "r"(b1));
}

__device__ __forceinline__ void named_bar(int id) {
    asm volatile("bar.sync %0, 64;" :: "r"(id) : "memory");
}

// ---------------------------------------------------------------------------
// One block = TWO instances; grid = 128 (1 block/SM).
//  quad 0 (warps 0,1): scan inst0   quad 1 (warps 2,3): scan inst1
//  quad 2 (warps 4,5): prod inst0   quad 3 (warps 6,7): prod inst1
// Scan: fp32 FFMA2, thread e owns Whh rows {e,64+e,128+e}; 1 named bar/step.
// Producer: tensor-core HMMA (fp16 in, f32 accum) xproj, 8 steps/group,
// D fragments scattered into the xq smem ring; volatile counters decouple.
// ---------------------------------------------------------------------------
__global__ void __launch_bounds__(256, 1) gru_kernel(
    const float* __restrict__ x,
    const float* __restrict__ h0,
    const float* __restrict__ Wih,
    const float* __restrict__ Whh,
    const float* __restrict__ bih,
    const float* __restrict__ bhh,
    float* __restrict__ out)
{
    const int tid  = threadIdx.x;
    const int quad = tid >> 6;     // 0..3
    const int e    = tid & 63;     // 0..63 within quad
    const int inst = quad & 1;     // instance 0/1
    const int bg   = 2 * blockIdx.x + inst;
    const int b    = bg >> 3;
    const int g    = bg & 7;

    __shared__ __align__(16) float xq[2][RS][192];  // per-inst xp ring
    __shared__ __align__(16) float hbuf[2][2][64];  // per-inst dbl-buffered h
    __shared__ int prodc[2];
    __shared__ int consc[2];

    if (tid < 2) { prodc[tid] = 0; consc[tid] = 0; }
    __syncthreads();

    volatile int* vprod = (volatile int*)&prodc[inst];
    volatile int* vcons = (volatile int*)&consc[inst];

    if (quad >= 2) {
        // ====================== PRODUCER (tensor core) ======================
        const int pw    = (tid >> 5) & 1;   // warp within quad: rows 0-95 / 96-191
        const int lane  = tid & 31;
        const int gid   = lane >> 2;        // 0..7  (= timestep within group)
        const int t4    = lane & 3;         // 0..3
        const int rbase = pw * 96;
        const int barid = 3 + inst;

        // A fragments: Wih rows [rbase, rbase+96), fp16, built once.
        uint32_t A[6][4][4];
        float bA[6], bB[6];
#pragma unroll
        for (int mt = 0; mt < 6; mt++) {
            const int r0 = rbase + mt * 16 + gid;
            const int r1 = r0 + 8;
            bA[mt] = bih[g * 192 + r0];
            bB[mt] = bih[g * 192 + r1];
#pragma unroll
            for (int kt = 0; kt < 4; kt++) {
                const int c0 = kt * 16 + 2 * t4;
                float2 w00 = *(const float2*)&Wih[((size_t)g * 192 + r0) * In + c0];
                float2 w10 = *(const float2*)&Wih[((size_t)g * 192 + r1) * In + c0];
                float2 w01 = *(const float2*)&Wih[((size_t)g * 192 + r0) * In + c0 + 8];
                float2 w11 = *(const float2*)&Wih[((size_t)g * 192 + r1) * In + c0 + 8];
                A[mt][kt][0] = f2_h2(w00.x, w00.y);
                A[mt][kt][1] = f2_h2(w10.x, w10.y);
                A[mt][kt][2] = f2_h2(w01.x, w01.y);
                A[mt][kt][3] = f2_h2(w11.x, w11.y);
            }
        }

        const float* xsrc = x + ((size_t)b * Tn) * XSTR + g * In;

        for (int p = 0; p < Tn / 8; p++) {
            const int lim = 8 * p - 8;
            if (lim > 0) { while (*vcons < lim) {} }

            // B fragments: x(t = 8p+gid), fp16 (loaded straight from gmem)
            const float* xg = xsrc + (size_t)(8 * p + gid) * XSTR;
            uint32_t Bf[4][2];
#pragma unroll
            for (int kt = 0; kt < 4; kt++) {
                const int k0 = kt * 16 + 2 * t4;
                float2 v0 = *(const float2*)&xg[k0];
                float2 v1 = *(const float2*)&xg[k0 + 8];
                Bf[kt][0] = f2_h2(v0.x, v0.y);
                Bf[kt][1] = f2_h2(v1.x, v1.y);
            }

            const int sb = (8 * p) & (RS - 1);
            float* ring = xq[inst][0];
#pragma unroll
            for (int mt = 0; mt < 6; mt++) {
                float d0 = bA[mt], d1 = bA[mt], d2 = bB[mt], d3 = bB[mt];
#pragma unroll
                for (int kt = 0; kt < 4; kt++)
                    mma_16x8x16(d0, d1, d2, d3,
                                A[mt][kt][0], A[mt][kt][1], A[mt][kt][2], A[mt][kt][3],
                                Bf[kt][0], Bf[kt][1]);
                const int r0 = rbase + mt * 16 + gid;
                const int s0 = sb + 2 * t4;
                ring[(size_t)s0 * 192 + r0]           = d0;
                ring[(size_t)(s0 + 1) * 192 + r0]     = d1;
                ring[(size_t)s0 * 192 + r0 + 8]       = d2;
                ring[(size_t)(s0 + 1) * 192 + r0 + 8] = d3;
            }
            __threadfence_block();
            named_bar(barid);   // both producer warps done with this group
            if (e == 0) *vprod = 8 * p + 8;
        }
        return;
    }

    // ============================== SCAN (fp32) ==============================
    const int barid = 1 + inst;
    ulonglong2 wr[16], wz[16], wn[16];
    {
        const ulonglong2* p;
        p = (const ulonglong2*)&Whh[((size_t)g * 192 + e) * Hn];
#pragma unroll
        for (int q = 0; q < 16; q++) wr[q] = p[q];
        p = (const ulonglong2*)&Whh[((size_t)g * 192 + 64 + e) * Hn];
#pragma unroll
        for (int q = 0; q < 16; q++) wz[q] = p[q];
        p = (const ulonglong2*)&Whh[((size_t)g * 192 + 128 + e) * Hn];
#pragma unroll
        for (int q = 0; q < 16; q++) wn[q] = p[q];
    }
    const float br = bhh[g * 192 + e];
    const float bz = bhh[g * 192 + 64 + e];
    const float bn = bhh[g * 192 + 128 + e];

    float hreg = h0[((size_t)g * Bn + b) * Hn + e];
    hbuf[inst][0][e] = hreg;
    float* outp = out + (size_t)b * Tn * (Gn * Hn) + g * Hn + e;

    named_bar(barid);   // hbuf[0] visible to both scan warps

    for (int t = 0; t < Tn; t++) {
        if ((t & 3) == 0) {
            if (e == 0) *vcons = t;
            const int need = (t + 4 < Tn) ? (t + 4) : Tn;
            while (*vprod < need) {}
            __threadfence_block();
        }

        // xq loads issued BEFORE the dot: LDS latency hides under FFMA2
        const float* slot = xq[inst][t & (RS - 1)];
        const float xr = slot[e];
        const float xz = slot[64 + e];
        const float xn = slot[128 + e];

        float3 d = dot64x3(wr, wz, wn, hbuf[inst][t & 1], br, bz, bn);

        float rr = fsig(xr + d.x);
        float zz = fsig(xz + d.y);
        float aa = xn + rr * d.z;
        float nn = __fmaf_rn(2.f, fsig(2.f * aa), -1.f);
        float hn = nn + zz * (hreg - nn);
        hreg = hn;
        hbuf[inst][(t + 1) & 1][e] = hn;
        __stcs(&outp[(size_t)t * (Gn * Hn)], hn);

        named_bar(barid);   // h(t) writes ordered before h(t+1) reads
    }

    out[(size_t)Bn * Tn * (Gn * Hn) + ((size_t)g * Bn + b) * Hn + e] = hreg;
}

// ---------------------------------------------------------------------------
extern "C" void kernel_launch(void* const* d_in, const int* in_sizes, int n_in,
                              void* d_out, int out_size)
{
    const float* x   = (const float*)d_in[0];
    const float* h0  = (const float*)d_in[1];
    const float* Wih = (const float*)d_in[2];
    const float* Whh = (const float*)d_in[3];
    const float* bih = (const float*)d_in[4];
    const float* bhh = (const float*)d_in[5];
    float* out = (float*)d_out;

    gru_kernel<<<(Bn * Gn) / 2, 256>>>(x, h0, Wih, Whh, bih, bhh, out);
}